// round 7
// baseline (speedup 1.0000x reference)
#include <cuda_runtime.h>
#include <cuda_fp16.h>
#include <cstdint>

#define NN   50000
#define EE   1600000
#define HH   8
#define FF   16
#define INF  256
#define HF   128
#define SLOPE 0.2f

#define MTILE 128
#define KC    64
#define LDT   72                               // padded fp16 row stride
#define GEMM_GRID ((NN + MTILE - 1) / MTILE)   // 391

// dynamic smem layout (bytes)
#define SM_A    0
#define SM_B    18432
#define SM_AL   36864
#define SM_AR   37376
#define SMEM_TOTAL 37888

// ---------------- scratch ----------------------------------------------------
__device__ __align__(16) __half g_feath[NN * HF];   // 12.8 MB
__device__ float g_el[NN * HH];
__device__ float g_er[NN * HH];
__device__ float g_mbias[FF];
__device__ int   g_cnt[NN];
__device__ int   g_off[NN + 1];
__device__ int   g_cursor[NN];
__device__ int   g_csr_src[EE];
__device__ int   g_is64;
__device__ __align__(16) __half g_Bh[HF * INF];     // W^T as fp16, [n][k] row-major

// ---------------- mma.sync wrapper -------------------------------------------
__device__ __forceinline__ void mma16816(float* d, unsigned a0, unsigned a1,
                                         unsigned a2, unsigned a3,
                                         unsigned b0, unsigned b1) {
    asm volatile(
        "mma.sync.aligned.m16n8k16.row.col.f32.f16.f16.f32 "
        "{%0,%1,%2,%3}, {%4,%5,%6,%7}, {%8,%9}, {%0,%1,%2,%3};"
        : "+f"(d[0]), "+f"(d[1]), "+f"(d[2]), "+f"(d[3])
        : "r"(a0), "r"(a1), "r"(a2), "r"(a3), "r"(b0), "r"(b1));
}

// ---------------- detect index dtype -----------------------------------------
__global__ void detect_kernel(const void* __restrict__ dstp) {
    if (threadIdx.x == 0 && blockIdx.x == 0) {
        const uint2* p = (const uint2*)dstp;
        unsigned any = 0;
        for (int i = 0; i < 256; i++) any |= p[i].y;
        g_is64 = (any == 0u) ? 1 : 0;
    }
}

// ---------------- zero counters + mean-bias ----------------------------------
__global__ void zero_cnt_kernel(const float* __restrict__ bias) {
    int i = blockIdx.x * blockDim.x + threadIdx.x;
    if (i < NN) g_cnt[i] = 0;
    if (i < FF) {
        float s = 0.f;
#pragma unroll
        for (int h = 0; h < HH; h++) s += bias[h * FF + i];
        g_mbias[i] = 0.125f * s;
    }
}

// ---------------- prep: W -> transposed fp16 image ([n][k]) -------------------
__global__ void prepB_kernel(const float* __restrict__ W) {
    int i = blockIdx.x * blockDim.x + threadIdx.x;   // 0..32767
    if (i >= HF * INF) return;
    int n = i >> 8;
    int k = i & 255;
    g_Bh[i] = __float2half_rn(W[(size_t)k * HF + n]);
}

// ---------------- dst histogram (reads raw indices) ---------------------------
__global__ void hist_kernel(const void* __restrict__ dstp) {
    int stride = gridDim.x * blockDim.x;
    int is64 = g_is64;
    for (int i = blockIdx.x * blockDim.x + threadIdx.x; i < EE; i += stride) {
        int d = is64 ? (int)((const long long*)dstp)[i] : ((const int*)dstp)[i];
        d = min(max(d, 0), NN - 1);
        atomicAdd(&g_cnt[d], 1);
    }
}

// ---------------- fp16 mma.sync GEMM + fused el/er + fp16 feat ----------------
__global__ __launch_bounds__(256, 2)
void gemm_kernel(const float* __restrict__ x,
                 const float* __restrict__ al,
                 const float* __restrict__ ar) {
    extern __shared__ char smem[];
    __half* sA = (__half*)(smem + SM_A);   // [128][72]
    __half* sB = (__half*)(smem + SM_B);   // [n=128][72]
    float* sal = (float*)(smem + SM_AL);
    float* sar = (float*)(smem + SM_AR);

    int tid  = threadIdx.x;
    int wid  = tid >> 5;
    int lane = tid & 31;
    int row0 = blockIdx.x * MTILE;
    int wm   = wid >> 2;     // 0..1  (64 rows)
    int wn   = wid & 3;      // 0..3  (32 cols)

    if (tid < HF) { sal[tid] = al[tid]; sar[tid] = ar[tid]; }

    float acc[4][4][4];
#pragma unroll
    for (int mt = 0; mt < 4; mt++)
#pragma unroll
        for (int nt = 0; nt < 4; nt++)
#pragma unroll
            for (int q = 0; q < 4; q++) acc[mt][nt][q] = 0.f;

    for (int c = 0; c < 4; c++) {
        int k0 = c * KC;
        __syncthreads();
        // stage A chunk (fp32 -> fp16), 2048 float4-loads
        for (int t = tid; t < 2048; t += 256) {
            int r  = t >> 4;
            int kq = (t & 15) * 4;
            float4 v = make_float4(0.f, 0.f, 0.f, 0.f);
            int gr = row0 + r;
            if (gr < NN) v = *(const float4*)(x + (size_t)gr * INF + k0 + kq);
            __half2 p0 = __floats2half2_rn(v.x, v.y);
            __half2 p1 = __floats2half2_rn(v.z, v.w);
            *(uint2*)&sA[r * LDT + kq] = make_uint2(*(unsigned*)&p0, *(unsigned*)&p1);
        }
        // stage B chunk (copy pre-built fp16 image), 1024 uint4
        for (int t = tid; t < 1024; t += 256) {
            int n  = t >> 3;
            int kq = (t & 7) * 8;
            *(uint4*)&sB[n * LDT + kq] = *(const uint4*)&g_Bh[n * INF + k0 + kq];
        }
        __syncthreads();

#pragma unroll
        for (int ks = 0; ks < 4; ks++) {
            int koff = ks * 16 + (lane & 3) * 2;
            unsigned bf[4][2];
#pragma unroll
            for (int nt = 0; nt < 4; nt++) {
                int n = (wn * 32 + nt * 8 + (lane >> 2)) * LDT + koff;
                bf[nt][0] = *(const unsigned*)&sB[n];
                bf[nt][1] = *(const unsigned*)&sB[n + 8];
            }
#pragma unroll
            for (int mt = 0; mt < 4; mt++) {
                int r = (wm * 64 + mt * 16 + (lane >> 2)) * LDT + koff;
                unsigned a0 = *(const unsigned*)&sA[r];
                unsigned a1 = *(const unsigned*)&sA[r + 8 * LDT];
                unsigned a2 = *(const unsigned*)&sA[r + 8];
                unsigned a3 = *(const unsigned*)&sA[r + 8 * LDT + 8];
#pragma unroll
                for (int nt = 0; nt < 4; nt++)
                    mma16816(acc[mt][nt], a0, a1, a2, a3, bf[nt][0], bf[nt][1]);
            }
        }
    }

    // epilogue: fp16 feat store + el/er from registers
#pragma unroll
    for (int mt = 0; mt < 4; mt++) {
        int rr0 = row0 + wm * 64 + mt * 16 + (lane >> 2);
        int rr1 = rr0 + 8;
        float el0[2] = {0.f, 0.f}, er0[2] = {0.f, 0.f};
        float el1[2] = {0.f, 0.f}, er1[2] = {0.f, 0.f};
#pragma unroll
        for (int nt = 0; nt < 4; nt++) {
            int col  = wn * 32 + nt * 8 + (lane & 3) * 2;
            int hsel = nt >> 1;
            float d0 = acc[mt][nt][0], d1 = acc[mt][nt][1];
            float d2 = acc[mt][nt][2], d3 = acc[mt][nt][3];
            el0[hsel] += d0 * sal[col] + d1 * sal[col + 1];
            er0[hsel] += d0 * sar[col] + d1 * sar[col + 1];
            el1[hsel] += d2 * sal[col] + d3 * sal[col + 1];
            er1[hsel] += d2 * sar[col] + d3 * sar[col + 1];
            if (rr0 < NN) {
                __half2 p = __floats2half2_rn(d0, d1);
                *(unsigned*)&g_feath[(size_t)rr0 * HF + col] = *(unsigned*)&p;
            }
            if (rr1 < NN) {
                __half2 p = __floats2half2_rn(d2, d3);
                *(unsigned*)&g_feath[(size_t)rr1 * HF + col] = *(unsigned*)&p;
            }
        }
#pragma unroll
        for (int s = 1; s <= 2; s <<= 1) {
            el0[0] += __shfl_xor_sync(0xffffffffu, el0[0], s);
            el0[1] += __shfl_xor_sync(0xffffffffu, el0[1], s);
            er0[0] += __shfl_xor_sync(0xffffffffu, er0[0], s);
            er0[1] += __shfl_xor_sync(0xffffffffu, er0[1], s);
            el1[0] += __shfl_xor_sync(0xffffffffu, el1[0], s);
            el1[1] += __shfl_xor_sync(0xffffffffu, el1[1], s);
            er1[0] += __shfl_xor_sync(0xffffffffu, er1[0], s);
            er1[1] += __shfl_xor_sync(0xffffffffu, er1[1], s);
        }
        if ((lane & 3) == 0) {
            if (rr0 < NN) {
                g_el[rr0 * HH + 2 * wn]     = el0[0];
                g_el[rr0 * HH + 2 * wn + 1] = el0[1];
                g_er[rr0 * HH + 2 * wn]     = er0[0];
                g_er[rr0 * HH + 2 * wn + 1] = er0[1];
            }
            if (rr1 < NN) {
                g_el[rr1 * HH + 2 * wn]     = el1[0];
                g_el[rr1 * HH + 2 * wn + 1] = el1[1];
                g_er[rr1 * HH + 2 * wn]     = er1[0];
                g_er[rr1 * HH + 2 * wn + 1] = er1[1];
            }
        }
    }
}

// ---------------- exclusive scan (single block, warp-shfl) --------------------
__global__ __launch_bounds__(1024) void scan_kernel() {
    __shared__ int wsum[32];
    __shared__ int carry_s;
    int lane = threadIdx.x & 31;
    int warp = threadIdx.x >> 5;
    if (threadIdx.x == 0) carry_s = 0;
    __syncthreads();
    for (int base = 0; base < NN; base += 1024) {
        int i = base + threadIdx.x;
        int v = (i < NN) ? g_cnt[i] : 0;
        int incl = v;
#pragma unroll
        for (int s = 1; s < 32; s <<= 1) {
            int t = __shfl_up_sync(0xffffffffu, incl, s);
            if (lane >= s) incl += t;
        }
        if (lane == 31) wsum[warp] = incl;
        __syncthreads();
        if (warp == 0) {
            int wv = wsum[lane];
            int wi = wv;
#pragma unroll
            for (int s = 1; s < 32; s <<= 1) {
                int t = __shfl_up_sync(0xffffffffu, wi, s);
                if (lane >= s) wi += t;
            }
            wsum[lane] = wi - wv;
        }
        __syncthreads();
        int excl = incl - v + wsum[warp] + carry_s;
        if (i < NN) { g_off[i] = excl; g_cursor[i] = excl; }
        __syncthreads();
        if (threadIdx.x == 1023) carry_s = excl + v;
        __syncthreads();
    }
    if (threadIdx.x == 0) g_off[NN] = carry_s;
}

// ---------------- scatter edges into CSR (reads raw indices) ------------------
__global__ void scatter_kernel(const void* __restrict__ srcp,
                               const void* __restrict__ dstp) {
    int stride = gridDim.x * blockDim.x;
    int is64 = g_is64;
    for (int i = blockIdx.x * blockDim.x + threadIdx.x; i < EE; i += stride) {
        int s, d;
        if (is64) {
            s = (int)((const long long*)srcp)[i];
            d = (int)((const long long*)dstp)[i];
        } else {
            s = ((const int*)srcp)[i];
            d = ((const int*)dstp)[i];
        }
        s = min(max(s, 0), NN - 1);
        d = min(max(d, 0), NN - 1);
        int p = atomicAdd(&g_cursor[d], 1);
        g_csr_src[p] = s;
    }
}

// ---------------- fused softmax-aggregate + classifier ------------------------
__global__ __launch_bounds__(256) void agg_kernel(float* __restrict__ out) {
    int gtid = blockIdx.x * blockDim.x + threadIdx.x;
    int n    = gtid >> 5;
    int lane = gtid & 31;
    if (n >= NN) return;
    int half = lane >> 4;
    int sub  = lane & 15;
    unsigned gmask = half ? 0xFFFF0000u : 0x0000FFFFu;

    float ern = (sub < HH) ? g_er[n * HH + sub] : 0.f;
    int beg = g_off[n], end = g_off[n + 1];

    float acc[8];
#pragma unroll
    for (int k = 0; k < 8; k++) acc[k] = 0.f;
    float ssum = 0.f;

    for (int i = beg + half; i < end; i += 2) {
        int sv = g_csr_src[i];
        float exv = 0.f;
        if (sub < HH) {
            float e = g_el[sv * HH + sub] + ern;
            e = fmaxf(e, 0.f) + SLOPE * fminf(e, 0.f);
            exv = __expf(e);
            ssum += exv;
        }
        float exh = __shfl_sync(gmask, exv, (half << 4) + (sub >> 1));
        uint4 f = *reinterpret_cast<const uint4*>(g_feath + (size_t)sv * HF + sub * 8);
        float2 v0 = __half22float2(*reinterpret_cast<__half2*>(&f.x));
        float2 v1 = __half22float2(*reinterpret_cast<__half2*>(&f.y));
        float2 v2 = __half22float2(*reinterpret_cast<__half2*>(&f.z));
        float2 v3 = __half22float2(*reinterpret_cast<__half2*>(&f.w));
        acc[0] += exh * v0.x; acc[1] += exh * v0.y;
        acc[2] += exh * v1.x; acc[3] += exh * v1.y;
        acc[4] += exh * v2.x; acc[5] += exh * v2.y;
        acc[6] += exh * v3.x; acc[7] += exh * v3.y;
    }
    __syncwarp();

#pragma unroll
    for (int k = 0; k < 8; k++) acc[k] += __shfl_xor_sync(0xffffffffu, acc[k], 16);
    ssum += __shfl_xor_sync(0xffffffffu, ssum, 16);

    float inv = 0.f;
    if (sub < HH) inv = 1.f / fmaxf(ssum, 1e-9f);
    float invh = __shfl_sync(0xffffffffu, inv, (half << 4) + (sub >> 1));
#pragma unroll
    for (int k = 0; k < 8; k++) acc[k] *= invh;

#pragma unroll
    for (int d = 2; d < 16; d <<= 1)
#pragma unroll
        for (int k = 0; k < 8; k++) acc[k] += __shfl_xor_sync(0xffffffffu, acc[k], d);

    if (lane < 2) {
        float4 o0, o1;
        o0.x = acc[0] * 0.125f + g_mbias[lane * 8 + 0];
        o0.y = acc[1] * 0.125f + g_mbias[lane * 8 + 1];
        o0.z = acc[2] * 0.125f + g_mbias[lane * 8 + 2];
        o0.w = acc[3] * 0.125f + g_mbias[lane * 8 + 3];
        o1.x = acc[4] * 0.125f + g_mbias[lane * 8 + 4];
        o1.y = acc[5] * 0.125f + g_mbias[lane * 8 + 5];
        o1.z = acc[6] * 0.125f + g_mbias[lane * 8 + 6];
        o1.w = acc[7] * 0.125f + g_mbias[lane * 8 + 7];
        ((float4*)out)[n * 4 + lane * 2 + 0] = o0;
        ((float4*)out)[n * 4 + lane * 2 + 1] = o1;
    }
}

// ---------------- launch ------------------------------------------------------
extern "C" void kernel_launch(void* const* d_in, const int* in_sizes, int n_in,
                              void* d_out, int out_size) {
    const float* x    = (const float*)d_in[0];
    const float* W    = (const float*)d_in[1];
    const float* al   = (const float*)d_in[2];
    const float* ar   = (const float*)d_in[3];
    const float* bias = (const float*)d_in[4];
    const void*  src  = d_in[5];
    const void*  dst  = d_in[6];
    float* out = (float*)d_out;

    cudaFuncSetAttribute(gemm_kernel, cudaFuncAttributeMaxDynamicSharedMemorySize, SMEM_TOTAL);

    detect_kernel<<<1, 32>>>(dst);
    zero_cnt_kernel<<<(NN + 255) / 256, 256>>>(bias);
    prepB_kernel<<<128, 256>>>(W);
    hist_kernel<<<2048, 256>>>(dst);
    gemm_kernel<<<GEMM_GRID, 256, SMEM_TOTAL>>>(x, al, ar);
    scan_kernel<<<1, 1024>>>();
    scatter_kernel<<<2048, 256>>>(src, dst);
    agg_kernel<<<(NN * 32 + 255) / 256, 256>>>(out);
}

// round 8
// speedup vs baseline: 1.2010x; 1.2010x over previous
#include <cuda_runtime.h>
#include <cuda_fp16.h>
#include <cstdint>

#define NN   50000
#define EE   1600000
#define HH   8
#define FF   16
#define INF  256
#define HF   128
#define SLOPE 0.2f

#define GEMM_BLOCKS 1563          // (NN+31)/32
#define HIST_BLOCKS 512

// ---------------- scratch ----------------------------------------------------
__device__ __align__(16) __half g_feath[NN * HF];   // 12.8 MB
__device__ float g_el[NN * HH];
__device__ float g_er[NN * HH];
__device__ float g_mbias[FF];
__device__ int   g_cnt[NN];
__device__ int   g_off[NN + 1];
__device__ int   g_cursor[NN];
__device__ int   g_csr_src[EE];
__device__ int   g_is64;

// ---------------- init: zero counters + mean-bias + dtype detect -------------
__global__ void init_kernel(const float* __restrict__ bias,
                            const void* __restrict__ dstp) {
    int i = blockIdx.x * blockDim.x + threadIdx.x;
    if (i < NN) g_cnt[i] = 0;
    if (i < FF) {
        float s = 0.f;
#pragma unroll
        for (int h = 0; h < HH; h++) s += bias[h * FF + i];
        g_mbias[i] = 0.125f * s;
    }
    if (i == 0) {
        const uint2* p = (const uint2*)dstp;
        unsigned any = 0;
        for (int k = 0; k < 256; k++) any |= p[k].y;
        g_is64 = (any == 0u) ? 1 : 0;
    }
}

// ---------------- merged: SIMT GEMM tiles + dst histogram ---------------------
// blocks [0, GEMM_BLOCKS): 32-row GEMM tile with fused el/er + fp16 feat store
// blocks [GEMM_BLOCKS, +HIST_BLOCKS): histogram of dst (overlaps with GEMM)
__global__ __launch_bounds__(256) void gemmhist_kernel(const float* __restrict__ x,
                                                       const float* __restrict__ W,
                                                       const float* __restrict__ al,
                                                       const float* __restrict__ ar,
                                                       const void* __restrict__ dstp) {
    __shared__ float xs[32][32];
    __shared__ float ws[32][HF];

    if (blockIdx.x >= GEMM_BLOCKS) {
        // ---- histogram role (vectorized 2 edges/iter) ----
        int bid    = blockIdx.x - GEMM_BLOCKS;
        int stride = HIST_BLOCKS * blockDim.x;
        int is64   = g_is64;
        for (int i = bid * blockDim.x + threadIdx.x; i < EE / 2; i += stride) {
            int d0, d1;
            if (is64) {
                longlong2 v = ((const longlong2*)dstp)[i];
                d0 = (int)v.x; d1 = (int)v.y;
            } else {
                int2 v = ((const int2*)dstp)[i];
                d0 = v.x; d1 = v.y;
            }
            d0 = min(max(d0, 0), NN - 1);
            d1 = min(max(d1, 0), NN - 1);
            atomicAdd(&g_cnt[d0], 1);
            atomicAdd(&g_cnt[d1], 1);
        }
        return;
    }

    // ---- GEMM role ----
    int tid  = threadIdx.x;
    int row0 = blockIdx.x * 32;
    int tcol = tid & 31;
    int trow = tid >> 5;

    float acc[4][4];
#pragma unroll
    for (int r = 0; r < 4; r++)
#pragma unroll
        for (int c = 0; c < 4; c++) acc[r][c] = 0.f;

    for (int k0 = 0; k0 < INF; k0 += 32) {
#pragma unroll
        for (int i = 0; i < 4; i++) {
            int idx = tid + i * 256;
            int r = idx >> 5, k = idx & 31;
            int gr = row0 + r;
            xs[r][k] = (gr < NN) ? x[(size_t)gr * INF + k0 + k] : 0.f;
        }
#pragma unroll
        for (int i = 0; i < 4; i++) {
            int idx = tid + i * 256;
            int k = idx >> 5, c4 = idx & 31;
            ((float4*)ws[k])[c4] = ((const float4*)(W + (size_t)(k0 + k) * HF))[c4];
        }
        __syncthreads();
#pragma unroll
        for (int kk = 0; kk < 32; kk++) {
            float4 b = ((float4*)ws[kk])[tcol];
            float a0 = xs[trow * 4 + 0][kk];
            float a1 = xs[trow * 4 + 1][kk];
            float a2 = xs[trow * 4 + 2][kk];
            float a3 = xs[trow * 4 + 3][kk];
            acc[0][0] += a0 * b.x; acc[0][1] += a0 * b.y; acc[0][2] += a0 * b.z; acc[0][3] += a0 * b.w;
            acc[1][0] += a1 * b.x; acc[1][1] += a1 * b.y; acc[1][2] += a1 * b.z; acc[1][3] += a1 * b.w;
            acc[2][0] += a2 * b.x; acc[2][1] += a2 * b.y; acc[2][2] += a2 * b.z; acc[2][3] += a2 * b.w;
            acc[3][0] += a3 * b.x; acc[3][1] += a3 * b.y; acc[3][2] += a3 * b.z; acc[3][3] += a3 * b.w;
        }
        __syncthreads();
    }

    // epilogue: fp16 feat store + fused el/er (exact fp32 accumulators)
    float4 al4 = ((const float4*)al)[tcol];
    float4 ar4 = ((const float4*)ar)[tcol];
#pragma unroll
    for (int r = 0; r < 4; r++) {
        int gr = row0 + trow * 4 + r;
        float pl = acc[r][0] * al4.x + acc[r][1] * al4.y + acc[r][2] * al4.z + acc[r][3] * al4.w;
        float pr = acc[r][0] * ar4.x + acc[r][1] * ar4.y + acc[r][2] * ar4.z + acc[r][3] * ar4.w;
        pl += __shfl_xor_sync(0xffffffffu, pl, 1);
        pl += __shfl_xor_sync(0xffffffffu, pl, 2);
        pr += __shfl_xor_sync(0xffffffffu, pr, 1);
        pr += __shfl_xor_sync(0xffffffffu, pr, 2);
        if (gr < NN) {
            if ((tcol & 3) == 0) {
                g_el[gr * HH + (tcol >> 2)] = pl;
                g_er[gr * HH + (tcol >> 2)] = pr;
            }
            __half2 p0 = __floats2half2_rn(acc[r][0], acc[r][1]);
            __half2 p1 = __floats2half2_rn(acc[r][2], acc[r][3]);
            uint2 pk;
            pk.x = *reinterpret_cast<unsigned*>(&p0);
            pk.y = *reinterpret_cast<unsigned*>(&p1);
            *reinterpret_cast<uint2*>(g_feath + (size_t)gr * HF + tcol * 4) = pk;
        }
    }
}

// ---------------- exclusive scan (single block, warp-shfl) --------------------
__global__ __launch_bounds__(1024) void scan_kernel() {
    __shared__ int wsum[32];
    __shared__ int carry_s;
    int lane = threadIdx.x & 31;
    int warp = threadIdx.x >> 5;
    if (threadIdx.x == 0) carry_s = 0;
    __syncthreads();
    for (int base = 0; base < NN; base += 1024) {
        int i = base + threadIdx.x;
        int v = (i < NN) ? g_cnt[i] : 0;
        int incl = v;
#pragma unroll
        for (int s = 1; s < 32; s <<= 1) {
            int t = __shfl_up_sync(0xffffffffu, incl, s);
            if (lane >= s) incl += t;
        }
        if (lane == 31) wsum[warp] = incl;
        __syncthreads();
        if (warp == 0) {
            int wv = wsum[lane];
            int wi = wv;
#pragma unroll
            for (int s = 1; s < 32; s <<= 1) {
                int t = __shfl_up_sync(0xffffffffu, wi, s);
                if (lane >= s) wi += t;
            }
            wsum[lane] = wi - wv;
        }
        __syncthreads();
        int excl = incl - v + wsum[warp] + carry_s;
        if (i < NN) { g_off[i] = excl; g_cursor[i] = excl; }
        __syncthreads();
        if (threadIdx.x == 1023) carry_s = excl + v;
        __syncthreads();
    }
    if (threadIdx.x == 0) g_off[NN] = carry_s;
}

// ---------------- scatter edges into CSR (vectorized raw reads) ---------------
__global__ void scatter_kernel(const void* __restrict__ srcp,
                               const void* __restrict__ dstp) {
    int stride = gridDim.x * blockDim.x;
    int is64 = g_is64;
    for (int i = blockIdx.x * blockDim.x + threadIdx.x; i < EE / 2; i += stride) {
        int s0, s1, d0, d1;
        if (is64) {
            longlong2 sv = ((const longlong2*)srcp)[i];
            longlong2 dv = ((const longlong2*)dstp)[i];
            s0 = (int)sv.x; s1 = (int)sv.y;
            d0 = (int)dv.x; d1 = (int)dv.y;
        } else {
            int2 sv = ((const int2*)srcp)[i];
            int2 dv = ((const int2*)dstp)[i];
            s0 = sv.x; s1 = sv.y;
            d0 = dv.x; d1 = dv.y;
        }
        s0 = min(max(s0, 0), NN - 1);
        s1 = min(max(s1, 0), NN - 1);
        d0 = min(max(d0, 0), NN - 1);
        d1 = min(max(d1, 0), NN - 1);
        int p0 = atomicAdd(&g_cursor[d0], 1);
        g_csr_src[p0] = s0;
        int p1 = atomicAdd(&g_cursor[d1], 1);
        g_csr_src[p1] = s1;
    }
}

// ---------------- fused softmax-aggregate + classifier ------------------------
// One warp per dst node; four 8-lane groups, each handling one edge at a time.
// Lane sub (0..7) = head for exp; loads cols [8sub..8sub+7] and [64+8sub..+7].
__global__ __launch_bounds__(256) void agg_kernel(float* __restrict__ out) {
    int gtid = blockIdx.x * blockDim.x + threadIdx.x;
    int n    = gtid >> 5;
    int lane = gtid & 31;
    if (n >= NN) return;
    int g   = lane >> 3;          // group 0..3
    int sub = lane & 7;           // head
    unsigned gm = 0xFFu << (g * 8);

    float ern = g_er[n * HH + sub];
    int beg = g_off[n], end = g_off[n + 1];

    float accL[8], accH[8];
#pragma unroll
    for (int k = 0; k < 8; k++) { accL[k] = 0.f; accH[k] = 0.f; }
    float ssum = 0.f;

    for (int i = beg + g; i < end; i += 4) {
        int sv = g_csr_src[i];
        float e = g_el[sv * HH + sub] + ern;
        e = fmaxf(e, 0.f) + SLOPE * fminf(e, 0.f);
        float exv = __expf(e);
        ssum += exv;
        float exL = __shfl_sync(gm, exv, (g << 3) + (sub >> 1));
        float exH = __shfl_sync(gm, exv, (g << 3) + 4 + (sub >> 1));
        const uint4* fp = (const uint4*)(g_feath + (size_t)sv * HF);
        uint4 f0 = fp[sub];
        uint4 f1 = fp[8 + sub];
        float2 a0 = __half22float2(*reinterpret_cast<__half2*>(&f0.x));
        float2 a1 = __half22float2(*reinterpret_cast<__half2*>(&f0.y));
        float2 a2 = __half22float2(*reinterpret_cast<__half2*>(&f0.z));
        float2 a3 = __half22float2(*reinterpret_cast<__half2*>(&f0.w));
        float2 b0 = __half22float2(*reinterpret_cast<__half2*>(&f1.x));
        float2 b1 = __half22float2(*reinterpret_cast<__half2*>(&f1.y));
        float2 b2 = __half22float2(*reinterpret_cast<__half2*>(&f1.z));
        float2 b3 = __half22float2(*reinterpret_cast<__half2*>(&f1.w));
        accL[0] += exL * a0.x; accL[1] += exL * a0.y;
        accL[2] += exL * a1.x; accL[3] += exL * a1.y;
        accL[4] += exL * a2.x; accL[5] += exL * a2.y;
        accL[6] += exL * a3.x; accL[7] += exL * a3.y;
        accH[0] += exH * b0.x; accH[1] += exH * b0.y;
        accH[2] += exH * b1.x; accH[3] += exH * b1.y;
        accH[4] += exH * b2.x; accH[5] += exH * b2.y;
        accH[6] += exH * b3.x; accH[7] += exH * b3.y;
    }
    __syncwarp(0xffffffffu);

    // combine the four groups
#pragma unroll
    for (int k = 0; k < 8; k++) {
        accL[k] += __shfl_xor_sync(0xffffffffu, accL[k], 8);
        accL[k] += __shfl_xor_sync(0xffffffffu, accL[k], 16);
        accH[k] += __shfl_xor_sync(0xffffffffu, accH[k], 8);
        accH[k] += __shfl_xor_sync(0xffffffffu, accH[k], 16);
    }
    ssum += __shfl_xor_sync(0xffffffffu, ssum, 8);
    ssum += __shfl_xor_sync(0xffffffffu, ssum, 16);

    // normalize: lane holds head 'sub' softmax sum
    float inv  = 1.f / fmaxf(ssum, 1e-9f);
    float invL = __shfl_sync(0xffffffffu, inv, (lane & 24) + (sub >> 1));
    float invH = __shfl_sync(0xffffffffu, inv, (lane & 24) + 4 + (sub >> 1));

    float v[8];
#pragma unroll
    for (int k = 0; k < 8; k++) v[k] = accL[k] * invL + accH[k] * invH;

    // head-sum: lanes of same parity within a group hold the same f-slot
#pragma unroll
    for (int k = 0; k < 8; k++) {
        v[k] += __shfl_xor_sync(0xffffffffu, v[k], 2);
        v[k] += __shfl_xor_sync(0xffffffffu, v[k], 4);
    }

    if (lane < 2) {
        float4 o0, o1;
        o0.x = v[0] * 0.125f + g_mbias[lane * 8 + 0];
        o0.y = v[1] * 0.125f + g_mbias[lane * 8 + 1];
        o0.z = v[2] * 0.125f + g_mbias[lane * 8 + 2];
        o0.w = v[3] * 0.125f + g_mbias[lane * 8 + 3];
        o1.x = v[4] * 0.125f + g_mbias[lane * 8 + 4];
        o1.y = v[5] * 0.125f + g_mbias[lane * 8 + 5];
        o1.z = v[6] * 0.125f + g_mbias[lane * 8 + 6];
        o1.w = v[7] * 0.125f + g_mbias[lane * 8 + 7];
        ((float4*)out)[n * 4 + lane * 2 + 0] = o0;
        ((float4*)out)[n * 4 + lane * 2 + 1] = o1;
    }
}

// ---------------- launch ------------------------------------------------------
extern "C" void kernel_launch(void* const* d_in, const int* in_sizes, int n_in,
                              void* d_out, int out_size) {
    const float* x    = (const float*)d_in[0];
    const float* W    = (const float*)d_in[1];
    const float* al   = (const float*)d_in[2];
    const float* ar   = (const float*)d_in[3];
    const float* bias = (const float*)d_in[4];
    const void*  src  = d_in[5];
    const void*  dst  = d_in[6];
    float* out = (float*)d_out;

    init_kernel<<<(NN + 255) / 256, 256>>>(bias, dst);
    gemmhist_kernel<<<GEMM_BLOCKS + HIST_BLOCKS, 256>>>(x, W, al, ar, dst);
    scan_kernel<<<1, 1024>>>();
    scatter_kernel<<<2048, 256>>>(src, dst);
    agg_kernel<<<(NN * 32 + 255) / 256, 256>>>(out);
}

// round 9
// speedup vs baseline: 1.4102x; 1.1742x over previous
#include <cuda_runtime.h>
#include <cuda_fp16.h>
#include <cstdint>

#define NN   50000
#define EE   1600000
#define HH   8
#define FF   16
#define INF  256
#define HF   128
#define SLOPE 0.2f

#define HB   512            // histogram blocks (first)
#define SB   256            // csr scan+scatter blocks (middle)
#define GB   1563           // gemm blocks (last)
#define NPB  196            // nodes per csr block (256*196 >= 50000)

// ---------------- scratch ----------------------------------------------------
__device__ __align__(16) __half g_feath[NN * HF];   // 12.8 MB
__device__ __half g_elh[NN * HH];
__device__ __half g_erh[NN * HH];
__device__ float g_mbias[FF];
__device__ int   g_cnt[NN];
__device__ int   g_off[NN + 1];
__device__ int   g_cursor[NN];
__device__ int   g_csr_src[EE];
__device__ int   g_is64;
__device__ int   g_done_hist;
__device__ int   g_doneA;
__device__ int   g_doneB;
__device__ int   g_blocksum[SB];

// ---------------- init: zero state + mean-bias + dtype detect -----------------
__global__ void init_kernel(const float* __restrict__ bias,
                            const void* __restrict__ dstp) {
    int i = blockIdx.x * blockDim.x + threadIdx.x;
    if (i < NN) g_cnt[i] = 0;
    if (i < FF) {
        float s = 0.f;
#pragma unroll
        for (int h = 0; h < HH; h++) s += bias[h * FF + i];
        g_mbias[i] = 0.125f * s;
    }
    if (i == 0) {
        const uint2* p = (const uint2*)dstp;
        unsigned any = 0;
        for (int k = 0; k < 256; k++) any |= p[k].y;
        g_is64 = (any == 0u) ? 1 : 0;
        g_done_hist = 0;
        g_doneA = 0;
        g_doneB = 0;
        g_off[NN] = EE;      // total edges is invariant
    }
}

// ---------------- mega kernel: hist | scan+scatter | gemm ---------------------
__global__ __launch_bounds__(256, 3)
void mega_kernel(const float* __restrict__ x,
                 const float* __restrict__ W,
                 const float* __restrict__ al,
                 const float* __restrict__ ar,
                 const void* __restrict__ srcp,
                 const void* __restrict__ dstp) {
    __shared__ float xs[32][32];
    __shared__ float ws[32][HF];
    __shared__ int   s_ws[8];
    __shared__ int   s_red[256];

    int b   = blockIdx.x;
    int tid = threadIdx.x;

    // ======================= role 1: histogram ================================
    if (b < HB) {
        int is64 = g_is64;
        int stride = HB * 256;
        for (int i = b * 256 + tid; i < EE / 2; i += stride) {
            int d0, d1;
            if (is64) {
                longlong2 v = ((const longlong2*)dstp)[i];
                d0 = (int)v.x; d1 = (int)v.y;
            } else {
                int2 v = ((const int2*)dstp)[i];
                d0 = v.x; d1 = v.y;
            }
            d0 = min(max(d0, 0), NN - 1);
            d1 = min(max(d1, 0), NN - 1);
            atomicAdd(&g_cnt[d0], 1);
            atomicAdd(&g_cnt[d1], 1);
        }
        __syncthreads();
        if (tid == 0) {
            __threadfence();
            atomicAdd(&g_done_hist, 1);
        }
        return;
    }

    // ======================= role 2: scan + scatter ===========================
    if (b < HB + SB) {
        int sb = b - HB;
        // wait for histogram completion
        if (tid == 0) {
            while (atomicAdd(&g_done_hist, 0) < HB) __nanosleep(128);
        }
        __syncthreads();

        // local inclusive scan of this block's NPB counts
        int base_i = sb * NPB;
        int i = base_i + tid;
        int v = (tid < NPB && i < NN) ? __ldcg(&g_cnt[i]) : 0;
        int lane = tid & 31, w = tid >> 5;
        int incl = v;
#pragma unroll
        for (int s = 1; s < 32; s <<= 1) {
            int t = __shfl_up_sync(0xffffffffu, incl, s);
            if (lane >= s) incl += t;
        }
        if (lane == 31) s_ws[w] = incl;
        __syncthreads();
        if (tid == 0) {
            int run = 0;
#pragma unroll
            for (int j = 0; j < 8; j++) { int t = s_ws[j]; s_ws[j] = run; run += t; }
        }
        __syncthreads();
        incl += s_ws[w];
        int lp = incl - v;                 // exclusive local prefix

        if (tid == 255) g_blocksum[sb] = incl;   // block total
        __threadfence();
        __syncthreads();
        if (tid == 0) {
            atomicAdd(&g_doneA, 1);
            while (atomicAdd(&g_doneA, 0) < SB) __nanosleep(128);
        }
        __syncthreads();

        // base = sum of earlier block totals
        s_red[tid] = (tid < sb) ? __ldcg(&g_blocksum[tid]) : 0;
        __syncthreads();
        for (int s = 128; s > 0; s >>= 1) {
            if (tid < s) s_red[tid] += s_red[tid + s];
            __syncthreads();
        }
        int base = s_red[0];

        if (tid < NPB && i < NN) {
            g_off[i]    = base + lp;
            g_cursor[i] = base + lp;
        }
        __threadfence();
        __syncthreads();
        if (tid == 0) {
            atomicAdd(&g_doneB, 1);
            while (atomicAdd(&g_doneB, 0) < SB) __nanosleep(128);
        }
        __syncthreads();

        // scatter
        int is64 = g_is64;
        int stride = SB * 256;
        for (int e = sb * 256 + tid; e < EE / 2; e += stride) {
            int s0, s1, d0, d1;
            if (is64) {
                longlong2 sv = ((const longlong2*)srcp)[e];
                longlong2 dv = ((const longlong2*)dstp)[e];
                s0 = (int)sv.x; s1 = (int)sv.y;
                d0 = (int)dv.x; d1 = (int)dv.y;
            } else {
                int2 sv = ((const int2*)srcp)[e];
                int2 dv = ((const int2*)dstp)[e];
                s0 = sv.x; s1 = sv.y;
                d0 = dv.x; d1 = dv.y;
            }
            s0 = min(max(s0, 0), NN - 1);
            s1 = min(max(s1, 0), NN - 1);
            d0 = min(max(d0, 0), NN - 1);
            d1 = min(max(d1, 0), NN - 1);
            int p0 = atomicAdd(&g_cursor[d0], 1);
            g_csr_src[p0] = s0;
            int p1 = atomicAdd(&g_cursor[d1], 1);
            g_csr_src[p1] = s1;
        }
        return;
    }

    // ======================= role 3: GEMM =====================================
    int gb   = b - HB - SB;
    int row0 = gb * 32;
    int tcol = tid & 31;
    int trow = tid >> 5;

    float acc[4][4];
#pragma unroll
    for (int r = 0; r < 4; r++)
#pragma unroll
        for (int c = 0; c < 4; c++) acc[r][c] = 0.f;

    for (int k0 = 0; k0 < INF; k0 += 32) {
#pragma unroll
        for (int i = 0; i < 4; i++) {
            int idx = tid + i * 256;
            int r = idx >> 5, k = idx & 31;
            int gr = row0 + r;
            xs[r][k] = (gr < NN) ? x[(size_t)gr * INF + k0 + k] : 0.f;
        }
#pragma unroll
        for (int i = 0; i < 4; i++) {
            int idx = tid + i * 256;
            int k = idx >> 5, c4 = idx & 31;
            ((float4*)ws[k])[c4] = ((const float4*)(W + (size_t)(k0 + k) * HF))[c4];
        }
        __syncthreads();
#pragma unroll
        for (int kk = 0; kk < 32; kk++) {
            float4 bb = ((float4*)ws[kk])[tcol];
            float a0 = xs[trow * 4 + 0][kk];
            float a1 = xs[trow * 4 + 1][kk];
            float a2 = xs[trow * 4 + 2][kk];
            float a3 = xs[trow * 4 + 3][kk];
            acc[0][0] += a0 * bb.x; acc[0][1] += a0 * bb.y; acc[0][2] += a0 * bb.z; acc[0][3] += a0 * bb.w;
            acc[1][0] += a1 * bb.x; acc[1][1] += a1 * bb.y; acc[1][2] += a1 * bb.z; acc[1][3] += a1 * bb.w;
            acc[2][0] += a2 * bb.x; acc[2][1] += a2 * bb.y; acc[2][2] += a2 * bb.z; acc[2][3] += a2 * bb.w;
            acc[3][0] += a3 * bb.x; acc[3][1] += a3 * bb.y; acc[3][2] += a3 * bb.z; acc[3][3] += a3 * bb.w;
        }
        __syncthreads();
    }

    // epilogue: fp16 feat store + fused el/er (fp32 accumulators, fp16 store)
    float4 al4 = ((const float4*)al)[tcol];
    float4 ar4 = ((const float4*)ar)[tcol];
#pragma unroll
    for (int r = 0; r < 4; r++) {
        int gr = row0 + trow * 4 + r;
        float pl = acc[r][0] * al4.x + acc[r][1] * al4.y + acc[r][2] * al4.z + acc[r][3] * al4.w;
        float pr = acc[r][0] * ar4.x + acc[r][1] * ar4.y + acc[r][2] * ar4.z + acc[r][3] * ar4.w;
        pl += __shfl_xor_sync(0xffffffffu, pl, 1);
        pl += __shfl_xor_sync(0xffffffffu, pl, 2);
        pr += __shfl_xor_sync(0xffffffffu, pr, 1);
        pr += __shfl_xor_sync(0xffffffffu, pr, 2);
        if (gr < NN) {
            if ((tcol & 3) == 0) {
                g_elh[gr * HH + (tcol >> 2)] = __float2half_rn(pl);
                g_erh[gr * HH + (tcol >> 2)] = __float2half_rn(pr);
            }
            __half2 p0 = __floats2half2_rn(acc[r][0], acc[r][1]);
            __half2 p1 = __floats2half2_rn(acc[r][2], acc[r][3]);
            uint2 pk;
            pk.x = *reinterpret_cast<unsigned*>(&p0);
            pk.y = *reinterpret_cast<unsigned*>(&p1);
            *reinterpret_cast<uint2*>(g_feath + (size_t)gr * HF + tcol * 4) = pk;
        }
    }
}

// ---------------- fused softmax-aggregate + classifier ------------------------
// One warp per dst node; four 8-lane groups, each handling one edge at a time.
__global__ __launch_bounds__(256) void agg_kernel(float* __restrict__ out) {
    int gtid = blockIdx.x * blockDim.x + threadIdx.x;
    int n    = gtid >> 5;
    int lane = gtid & 31;
    if (n >= NN) return;
    int g   = lane >> 3;          // group 0..3
    int sub = lane & 7;           // head
    unsigned gm = 0xFFu << (g * 8);

    float ern = __half2float(g_erh[n * HH + sub]);
    int beg = g_off[n], end = g_off[n + 1];

    float accL[8], accH[8];
#pragma unroll
    for (int k = 0; k < 8; k++) { accL[k] = 0.f; accH[k] = 0.f; }
    float ssum = 0.f;

    int i  = beg + g;
    int sv = (i < end) ? g_csr_src[i] : -1;
    while (sv >= 0) {
        int ni  = i + 4;
        int nsv = (ni < end) ? g_csr_src[ni] : -1;   // prefetch next edge
        // issue feat loads early
        const uint4* fp = (const uint4*)(g_feath + (size_t)sv * HF);
        uint4 f0 = fp[sub];
        uint4 f1 = fp[8 + sub];
        float e = __half2float(g_elh[sv * HH + sub]) + ern;
        e = fmaxf(e, 0.f) + SLOPE * fminf(e, 0.f);
        float exv = __expf(e);
        ssum += exv;
        float exL = __shfl_sync(gm, exv, (g << 3) + (sub >> 1));
        float exH = __shfl_sync(gm, exv, (g << 3) + 4 + (sub >> 1));
        float2 a0 = __half22float2(*reinterpret_cast<__half2*>(&f0.x));
        float2 a1 = __half22float2(*reinterpret_cast<__half2*>(&f0.y));
        float2 a2 = __half22float2(*reinterpret_cast<__half2*>(&f0.z));
        float2 a3 = __half22float2(*reinterpret_cast<__half2*>(&f0.w));
        float2 b0 = __half22float2(*reinterpret_cast<__half2*>(&f1.x));
        float2 b1 = __half22float2(*reinterpret_cast<__half2*>(&f1.y));
        float2 b2 = __half22float2(*reinterpret_cast<__half2*>(&f1.z));
        float2 b3 = __half22float2(*reinterpret_cast<__half2*>(&f1.w));
        accL[0] += exL * a0.x; accL[1] += exL * a0.y;
        accL[2] += exL * a1.x; accL[3] += exL * a1.y;
        accL[4] += exL * a2.x; accL[5] += exL * a2.y;
        accL[6] += exL * a3.x; accL[7] += exL * a3.y;
        accH[0] += exH * b0.x; accH[1] += exH * b0.y;
        accH[2] += exH * b1.x; accH[3] += exH * b1.y;
        accH[4] += exH * b2.x; accH[5] += exH * b2.y;
        accH[6] += exH * b3.x; accH[7] += exH * b3.y;
        i = ni; sv = nsv;
    }
    __syncwarp(0xffffffffu);

    // combine the four groups
#pragma unroll
    for (int k = 0; k < 8; k++) {
        accL[k] += __shfl_xor_sync(0xffffffffu, accL[k], 8);
        accL[k] += __shfl_xor_sync(0xffffffffu, accL[k], 16);
        accH[k] += __shfl_xor_sync(0xffffffffu, accH[k], 8);
        accH[k] += __shfl_xor_sync(0xffffffffu, accH[k], 16);
    }
    ssum += __shfl_xor_sync(0xffffffffu, ssum, 8);
    ssum += __shfl_xor_sync(0xffffffffu, ssum, 16);

    float inv  = 1.f / fmaxf(ssum, 1e-9f);
    float invL = __shfl_sync(0xffffffffu, inv, (lane & 24) + (sub >> 1));
    float invH = __shfl_sync(0xffffffffu, inv, (lane & 24) + 4 + (sub >> 1));

    float v[8];
#pragma unroll
    for (int k = 0; k < 8; k++) v[k] = accL[k] * invL + accH[k] * invH;

#pragma unroll
    for (int k = 0; k < 8; k++) {
        v[k] += __shfl_xor_sync(0xffffffffu, v[k], 2);
        v[k] += __shfl_xor_sync(0xffffffffu, v[k], 4);
    }

    if (lane < 2) {
        float4 o0, o1;
        o0.x = v[0] * 0.125f + g_mbias[lane * 8 + 0];
        o0.y = v[1] * 0.125f + g_mbias[lane * 8 + 1];
        o0.z = v[2] * 0.125f + g_mbias[lane * 8 + 2];
        o0.w = v[3] * 0.125f + g_mbias[lane * 8 + 3];
        o1.x = v[4] * 0.125f + g_mbias[lane * 8 + 4];
        o1.y = v[5] * 0.125f + g_mbias[lane * 8 + 5];
        o1.z = v[6] * 0.125f + g_mbias[lane * 8 + 6];
        o1.w = v[7] * 0.125f + g_mbias[lane * 8 + 7];
        ((float4*)out)[n * 4 + lane * 2 + 0] = o0;
        ((float4*)out)[n * 4 + lane * 2 + 1] = o1;
    }
}

// ---------------- launch ------------------------------------------------------
extern "C" void kernel_launch(void* const* d_in, const int* in_sizes, int n_in,
                              void* d_out, int out_size) {
    const float* x    = (const float*)d_in[0];
    const float* W    = (const float*)d_in[1];
    const float* al   = (const float*)d_in[2];
    const float* ar   = (const float*)d_in[3];
    const float* bias = (const float*)d_in[4];
    const void*  src  = d_in[5];
    const void*  dst  = d_in[6];
    float* out = (float*)d_out;

    init_kernel<<<(NN + 255) / 256, 256>>>(bias, dst);
    mega_kernel<<<HB + SB + GB, 256>>>(x, W, al, ar, src, dst);
    agg_kernel<<<(NN * 32 + 255) / 256, 256>>>(out);
}

// round 10
// speedup vs baseline: 2.0494x; 1.4533x over previous
#include <cuda_runtime.h>
#include <cuda_fp16.h>
#include <cstdint>

#define NN   50000
#define EE   1600000
#define HH   8
#define FF   16
#define INF  256
#define HF   128
#define SLOPE 0.2f

#define HB   512            // histogram blocks (first)
#define SB   256            // csr scan+scatter blocks (middle)
#define NPB  196            // nodes per csr block
#define MTILE 128
#define KC    64
#define LDT   72            // padded fp16 row stride (144B rows, 16B-aligned)
#define GB ((NN + MTILE - 1) / MTILE)   // 391 gemm blocks (last)

// dynamic smem layout (bytes)
#define SM_A0 0
#define SM_B0 18432
#define SM_A1 36864
#define SM_B1 55296
#define SM_AL 73728
#define SM_AR 74240
#define SMEM_TOTAL 74752

// ---------------- scratch ----------------------------------------------------
__device__ __align__(16) __half g_xh[NN * INF];     // 25.6 MB fp16 x
__device__ __align__(16) __half g_Bh[HF * INF];     // W^T fp16 [n][k]
__device__ __align__(16) __half g_feath[NN * HF];   // 12.8 MB
__device__ __half g_elh[NN * HH];
__device__ __half g_erh[NN * HH];
__device__ float g_mbias[FF];
__device__ int   g_cnt[NN];
__device__ int   g_off[NN + 1];
__device__ int   g_cursor[NN];
__device__ int   g_csr_src[EE];
__device__ int   g_is64;
__device__ int   g_done_hist;
__device__ int   g_doneA;
__device__ int   g_doneB;
__device__ int   g_blocksum[SB];

// ---------------- ptx helpers -------------------------------------------------
__device__ __forceinline__ void mma16816(float* d, unsigned a0, unsigned a1,
                                         unsigned a2, unsigned a3,
                                         unsigned b0, unsigned b1) {
    asm volatile(
        "mma.sync.aligned.m16n8k16.row.col.f32.f16.f16.f32 "
        "{%0,%1,%2,%3}, {%4,%5,%6,%7}, {%8,%9}, {%0,%1,%2,%3};"
        : "+f"(d[0]), "+f"(d[1]), "+f"(d[2]), "+f"(d[3])
        : "r"(a0), "r"(a1), "r"(a2), "r"(a3), "r"(b0), "r"(b1));
}
__device__ __forceinline__ void cpa16(uint32_t s, const void* g) {
    asm volatile("cp.async.cg.shared.global [%0], [%1], 16;" :: "r"(s), "l"(g));
}
#define CP_COMMIT() asm volatile("cp.async.commit_group;" ::: "memory")
#define CP_WAIT1()  asm volatile("cp.async.wait_group 1;" ::: "memory")
#define CP_WAIT0()  asm volatile("cp.async.wait_group 0;" ::: "memory")

// ---------------- init: convert x->fp16, prepB, zero, detect ------------------
__global__ __launch_bounds__(256) void init_kernel(const float* __restrict__ bias,
                                                   const void* __restrict__ dstp,
                                                   const float* __restrict__ x,
                                                   const float* __restrict__ W) {
    int gid = blockIdx.x * 256 + threadIdx.x;
    int gs  = gridDim.x * 256;
    // convert x (float4 granularity)
    for (int i = gid; i < NN * INF / 4; i += gs) {
        float4 v = ((const float4*)x)[i];
        __half2 h0 = __floats2half2_rn(v.x, v.y);
        __half2 h1 = __floats2half2_rn(v.z, v.w);
        *(uint2*)&g_xh[(size_t)i * 4] =
            make_uint2(*(unsigned*)&h0, *(unsigned*)&h1);
    }
    // W -> transposed fp16 image [n][k]
    for (int i = gid; i < HF * INF; i += gs) {
        int n = i >> 8, k = i & 255;
        g_Bh[i] = __float2half_rn(W[(size_t)k * HF + n]);
    }
    // zero counters
    for (int i = gid; i < NN; i += gs) g_cnt[i] = 0;
    if (gid < FF) {
        float s = 0.f;
#pragma unroll
        for (int h = 0; h < HH; h++) s += bias[h * FF + gid];
        g_mbias[gid] = 0.125f * s;
    }
    // parallel dtype detect (block 0)
    if (blockIdx.x == 0) {
        __shared__ unsigned sany[8];
        unsigned v = ((const uint2*)dstp)[threadIdx.x].y;
#pragma unroll
        for (int s = 16; s > 0; s >>= 1) v |= __shfl_xor_sync(0xffffffffu, v, s);
        if ((threadIdx.x & 31) == 0) sany[threadIdx.x >> 5] = v;
        __syncthreads();
        if (threadIdx.x == 0) {
            unsigned t = 0;
#pragma unroll
            for (int j = 0; j < 8; j++) t |= sany[j];
            g_is64 = (t == 0u) ? 1 : 0;
            g_done_hist = 0;
            g_doneA = 0;
            g_doneB = 0;
            g_off[NN] = EE;
        }
    }
}

// ---------------- mega kernel: hist | scan+scatter | fp16-mma gemm ------------
__global__ __launch_bounds__(256, 2)
void mega_kernel(const float* __restrict__ al,
                 const float* __restrict__ ar,
                 const void* __restrict__ srcp,
                 const void* __restrict__ dstp) {
    extern __shared__ char smem[];
    __shared__ int s_ws[8];
    __shared__ int s_red[256];

    int b   = blockIdx.x;
    int tid = threadIdx.x;

    // ======================= role 1: histogram ================================
    if (b < HB) {
        int is64 = g_is64;
        int stride = HB * 256;
        for (int i = b * 256 + tid; i < EE / 2; i += stride) {
            int d0, d1;
            if (is64) {
                longlong2 v = ((const longlong2*)dstp)[i];
                d0 = (int)v.x; d1 = (int)v.y;
            } else {
                int2 v = ((const int2*)dstp)[i];
                d0 = v.x; d1 = v.y;
            }
            d0 = min(max(d0, 0), NN - 1);
            d1 = min(max(d1, 0), NN - 1);
            atomicAdd(&g_cnt[d0], 1);
            atomicAdd(&g_cnt[d1], 1);
        }
        __syncthreads();
        if (tid == 0) {
            __threadfence();
            atomicAdd(&g_done_hist, 1);
        }
        return;
    }

    // ======================= role 2: scan + scatter ===========================
    if (b < HB + SB) {
        int sb = b - HB;
        if (tid == 0) {
            while (atomicAdd(&g_done_hist, 0) < HB) __nanosleep(128);
        }
        __syncthreads();

        int i = sb * NPB + tid;
        int v = (tid < NPB && i < NN) ? __ldcg(&g_cnt[i]) : 0;
        int lane = tid & 31, w = tid >> 5;
        int incl = v;
#pragma unroll
        for (int s = 1; s < 32; s <<= 1) {
            int t = __shfl_up_sync(0xffffffffu, incl, s);
            if (lane >= s) incl += t;
        }
        if (lane == 31) s_ws[w] = incl;
        __syncthreads();
        if (tid == 0) {
            int run = 0;
#pragma unroll
            for (int j = 0; j < 8; j++) { int t = s_ws[j]; s_ws[j] = run; run += t; }
        }
        __syncthreads();
        incl += s_ws[w];
        int lp = incl - v;

        if (tid == 255) g_blocksum[sb] = incl;
        __threadfence();
        __syncthreads();
        if (tid == 0) {
            atomicAdd(&g_doneA, 1);
            while (atomicAdd(&g_doneA, 0) < SB) __nanosleep(128);
        }
        __syncthreads();

        s_red[tid] = (tid < sb) ? __ldcg(&g_blocksum[tid]) : 0;
        __syncthreads();
        for (int s = 128; s > 0; s >>= 1) {
            if (tid < s) s_red[tid] += s_red[tid + s];
            __syncthreads();
        }
        int base = s_red[0];

        if (tid < NPB && i < NN) {
            g_off[i]    = base + lp;
            g_cursor[i] = base + lp;
        }
        __threadfence();
        __syncthreads();
        if (tid == 0) {
            atomicAdd(&g_doneB, 1);
            while (atomicAdd(&g_doneB, 0) < SB) __nanosleep(128);
        }
        __syncthreads();

        int is64 = g_is64;
        int stride = SB * 256;
        for (int e = sb * 256 + tid; e < EE / 2; e += stride) {
            int s0, s1, d0, d1;
            if (is64) {
                longlong2 sv = ((const longlong2*)srcp)[e];
                longlong2 dv = ((const longlong2*)dstp)[e];
                s0 = (int)sv.x; s1 = (int)sv.y;
                d0 = (int)dv.x; d1 = (int)dv.y;
            } else {
                int2 sv = ((const int2*)srcp)[e];
                int2 dv = ((const int2*)dstp)[e];
                s0 = sv.x; s1 = sv.y;
                d0 = dv.x; d1 = dv.y;
            }
            s0 = min(max(s0, 0), NN - 1);
            s1 = min(max(s1, 0), NN - 1);
            d0 = min(max(d0, 0), NN - 1);
            d1 = min(max(d1, 0), NN - 1);
            int p0 = atomicAdd(&g_cursor[d0], 1);
            g_csr_src[p0] = s0;
            int p1 = atomicAdd(&g_cursor[d1], 1);
            g_csr_src[p1] = s1;
        }
        return;
    }

    // ======================= role 3: fp16 mma GEMM ============================
    int gb   = b - HB - SB;
    int row0 = gb * MTILE;
    int wid  = tid >> 5;
    int lane = tid & 31;
    int wm   = wid >> 2;     // 0..1 (64 rows)
    int wn   = wid & 3;      // 0..3 (32 cols)
    uint32_t sbase = (uint32_t)__cvta_generic_to_shared(smem);
    float* salf = (float*)(smem + SM_AL);
    float* sarf = (float*)(smem + SM_AR);

    if (tid < HF) { salf[tid] = al[tid]; sarf[tid] = ar[tid]; }

    float acc[4][4][4];
#pragma unroll
    for (int mt = 0; mt < 4; mt++)
#pragma unroll
        for (int nt = 0; nt < 4; nt++)
#pragma unroll
            for (int q = 0; q < 4; q++) acc[mt][nt][q] = 0.f;

    // chunk loader: A rows from g_xh, B rows from g_Bh (16B segments)
    auto load_chunk = [&](int buf, int c) {
        uint32_t abase = sbase + (buf ? SM_A1 : SM_A0);
        uint32_t bbase = sbase + (buf ? SM_B1 : SM_B0);
        for (int t = tid; t < 2048; t += 256) {
            int seg = t & 7;
            if (t < 1024) {
                int r  = t >> 3;
                int gr = row0 + r;
                if (gr < NN)
                    cpa16(abase + r * 144 + seg * 16,
                          g_xh + (size_t)gr * INF + c * KC + seg * 8);
            } else {
                int n = (t - 1024) >> 3;
                cpa16(bbase + n * 144 + seg * 16,
                      g_Bh + (size_t)n * INF + c * KC + seg * 8);
            }
        }
    };

    load_chunk(0, 0);
    CP_COMMIT();
    for (int c = 0; c < 4; c++) {
        if (c < 3) {
            load_chunk((c + 1) & 1, c + 1);
            CP_COMMIT();
            CP_WAIT1();
        } else {
            CP_WAIT0();
        }
        __syncthreads();
        __half* sA = (__half*)(smem + ((c & 1) ? SM_A1 : SM_A0));
        __half* sB = (__half*)(smem + ((c & 1) ? SM_B1 : SM_B0));
#pragma unroll
        for (int ks = 0; ks < 4; ks++) {
            int koff = ks * 16 + (lane & 3) * 2;
            unsigned bf[4][2];
#pragma unroll
            for (int nt = 0; nt < 4; nt++) {
                int n = (wn * 32 + nt * 8 + (lane >> 2)) * LDT + koff;
                bf[nt][0] = *(const unsigned*)&sB[n];
                bf[nt][1] = *(const unsigned*)&sB[n + 8];
            }
#pragma unroll
            for (int mt = 0; mt < 4; mt++) {
                int r = (wm * 64 + mt * 16 + (lane >> 2)) * LDT + koff;
                unsigned a0 = *(const unsigned*)&sA[r];
                unsigned a1 = *(const unsigned*)&sA[r + 8 * LDT];
                unsigned a2 = *(const unsigned*)&sA[r + 8];
                unsigned a3 = *(const unsigned*)&sA[r + 8 * LDT + 8];
#pragma unroll
                for (int nt = 0; nt < 4; nt++)
                    mma16816(acc[mt][nt], a0, a1, a2, a3, bf[nt][0], bf[nt][1]);
            }
        }
        __syncthreads();
    }

    // epilogue: fp16 feat store + el/er from registers (R6-proven mapping)
#pragma unroll
    for (int mt = 0; mt < 4; mt++) {
        int rr0 = row0 + wm * 64 + mt * 16 + (lane >> 2);
        int rr1 = rr0 + 8;
        float el0[2] = {0.f, 0.f}, er0[2] = {0.f, 0.f};
        float el1[2] = {0.f, 0.f}, er1[2] = {0.f, 0.f};
#pragma unroll
        for (int nt = 0; nt < 4; nt++) {
            int col  = wn * 32 + nt * 8 + (lane & 3) * 2;
            int hsel = nt >> 1;
            float d0 = acc[mt][nt][0], d1 = acc[mt][nt][1];
            float d2 = acc[mt][nt][2], d3 = acc[mt][nt][3];
            el0[hsel] += d0 * salf[col] + d1 * salf[col + 1];
            er0[hsel] += d0 * sarf[col] + d1 * sarf[col + 1];
            el1[hsel] += d2 * salf[col] + d3 * salf[col + 1];
            er1[hsel] += d2 * sarf[col] + d3 * sarf[col + 1];
            if (rr0 < NN) {
                __half2 p = __floats2half2_rn(d0, d1);
                *(unsigned*)&g_feath[(size_t)rr0 * HF + col] = *(unsigned*)&p;
            }
            if (rr1 < NN) {
                __half2 p = __floats2half2_rn(d2, d3);
                *(unsigned*)&g_feath[(size_t)rr1 * HF + col] = *(unsigned*)&p;
            }
        }
#pragma unroll
        for (int s = 1; s <= 2; s <<= 1) {
            el0[0] += __shfl_xor_sync(0xffffffffu, el0[0], s);
            el0[1] += __shfl_xor_sync(0xffffffffu, el0[1], s);
            er0[0] += __shfl_xor_sync(0xffffffffu, er0[0], s);
            er0[1] += __shfl_xor_sync(0xffffffffu, er0[1], s);
            el1[0] += __shfl_xor_sync(0xffffffffu, el1[0], s);
            el1[1] += __shfl_xor_sync(0xffffffffu, el1[1], s);
            er1[0] += __shfl_xor_sync(0xffffffffu, er1[0], s);
            er1[1] += __shfl_xor_sync(0xffffffffu, er1[1], s);
        }
        if ((lane & 3) == 0) {
            if (rr0 < NN) {
                g_elh[rr0 * HH + 2 * wn]     = __float2half_rn(el0[0]);
                g_elh[rr0 * HH + 2 * wn + 1] = __float2half_rn(el0[1]);
                g_erh[rr0 * HH + 2 * wn]     = __float2half_rn(er0[0]);
                g_erh[rr0 * HH + 2 * wn + 1] = __float2half_rn(er0[1]);
            }
            if (rr1 < NN) {
                g_elh[rr1 * HH + 2 * wn]     = __float2half_rn(el1[0]);
                g_elh[rr1 * HH + 2 * wn + 1] = __float2half_rn(el1[1]);
                g_erh[rr1 * HH + 2 * wn]     = __float2half_rn(er1[0]);
                g_erh[rr1 * HH + 2 * wn + 1] = __float2half_rn(er1[1]);
            }
        }
    }
}

// ---------------- fused softmax-aggregate + classifier ------------------------
__global__ __launch_bounds__(256) void agg_kernel(float* __restrict__ out) {
    int gtid = blockIdx.x * blockDim.x + threadIdx.x;
    int n    = gtid >> 5;
    int lane = gtid & 31;
    if (n >= NN) return;
    int g   = lane >> 3;
    int sub = lane & 7;
    unsigned gm = 0xFFu << (g * 8);

    float ern = __half2float(g_erh[n * HH + sub]);
    int beg = g_off[n], end = g_off[n + 1];

    float accL[8], accH[8];
#pragma unroll
    for (int k = 0; k < 8; k++) { accL[k] = 0.f; accH[k] = 0.f; }
    float ssum = 0.f;

    int i  = beg + g;
    int sv = (i < end) ? g_csr_src[i] : -1;
    while (sv >= 0) {
        int ni  = i + 4;
        int nsv = (ni < end) ? g_csr_src[ni] : -1;
        const uint4* fp = (const uint4*)(g_feath + (size_t)sv * HF);
        uint4 f0 = fp[sub];
        uint4 f1 = fp[8 + sub];
        float e = __half2float(g_elh[sv * HH + sub]) + ern;
        e = fmaxf(e, 0.f) + SLOPE * fminf(e, 0.f);
        float exv = __expf(e);
        ssum += exv;
        float exL = __shfl_sync(gm, exv, (g << 3) + (sub >> 1));
        float exH = __shfl_sync(gm, exv, (g << 3) + 4 + (sub >> 1));
        float2 a0 = __half22float2(*reinterpret_cast<__half2*>(&f0.x));
        float2 a1 = __half22float2(*reinterpret_cast<__half2*>(&f0.y));
        float2 a2 = __half22float2(*reinterpret_cast<__half2*>(&f0.z));
        float2 a3 = __half22float2(*reinterpret_cast<__half2*>(&f0.w));
        float2 b0 = __half22float2(*reinterpret_cast<__half2*>(&f1.x));
        float2 b1 = __half22float2(*reinterpret_cast<__half2*>(&f1.y));
        float2 b2 = __half22float2(*reinterpret_cast<__half2*>(&f1.z));
        float2 b3 = __half22float2(*reinterpret_cast<__half2*>(&f1.w));
        accL[0] += exL * a0.x; accL[1] += exL * a0.y;
        accL[2] += exL * a1.x; accL[3] += exL * a1.y;
        accL[4] += exL * a2.x; accL[5] += exL * a2.y;
        accL[6] += exL * a3.x; accL[7] += exL * a3.y;
        accH[0] += exH * b0.x; accH[1] += exH * b0.y;
        accH[2] += exH * b1.x; accH[3] += exH * b1.y;
        accH[4] += exH * b2.x; accH[5] += exH * b2.y;
        accH[6] += exH * b3.x; accH[7] += exH * b3.y;
        i = ni; sv = nsv;
    }
    __syncwarp(0xffffffffu);

#pragma unroll
    for (int k = 0; k < 8; k++) {
        accL[k] += __shfl_xor_sync(0xffffffffu, accL[k], 8);
        accL[k] += __shfl_xor_sync(0xffffffffu, accL[k], 16);
        accH[k] += __shfl_xor_sync(0xffffffffu, accH[k], 8);
        accH[k] += __shfl_xor_sync(0xffffffffu, accH[k], 16);
    }
    ssum += __shfl_xor_sync(0xffffffffu, ssum, 8);
    ssum += __shfl_xor_sync(0xffffffffu, ssum, 16);

    float inv  = 1.f / fmaxf(ssum, 1e-9f);
    float invL = __shfl_sync(0xffffffffu, inv, (lane & 24) + (sub >> 1));
    float invH = __shfl_sync(0xffffffffu, inv, (lane & 24) + 4 + (sub >> 1));

    float v[8];
#pragma unroll
    for (int k = 0; k < 8; k++) v[k] = accL[k] * invL + accH[k] * invH;

#pragma unroll
    for (int k = 0; k < 8; k++) {
        v[k] += __shfl_xor_sync(0xffffffffu, v[k], 2);
        v[k] += __shfl_xor_sync(0xffffffffu, v[k], 4);
    }

    if (lane < 2) {
        float4 o0, o1;
        o0.x = v[0] * 0.125f + g_mbias[lane * 8 + 0];
        o0.y = v[1] * 0.125f + g_mbias[lane * 8 + 1];
        o0.z = v[2] * 0.125f + g_mbias[lane * 8 + 2];
        o0.w = v[3] * 0.125f + g_mbias[lane * 8 + 3];
        o1.x = v[4] * 0.125f + g_mbias[lane * 8 + 4];
        o1.y = v[5] * 0.125f + g_mbias[lane * 8 + 5];
        o1.z = v[6] * 0.125f + g_mbias[lane * 8 + 6];
        o1.w = v[7] * 0.125f + g_mbias[lane * 8 + 7];
        ((float4*)out)[n * 4 + lane * 2 + 0] = o0;
        ((float4*)out)[n * 4 + lane * 2 + 1] = o1;
    }
}

// ---------------- launch ------------------------------------------------------
extern "C" void kernel_launch(void* const* d_in, const int* in_sizes, int n_in,
                              void* d_out, int out_size) {
    const float* x    = (const float*)d_in[0];
    const float* W    = (const float*)d_in[1];
    const float* al   = (const float*)d_in[2];
    const float* ar   = (const float*)d_in[3];
    const float* bias = (const float*)d_in[4];
    const void*  src  = d_in[5];
    const void*  dst  = d_in[6];
    float* out = (float*)d_out;

    cudaFuncSetAttribute(mega_kernel, cudaFuncAttributeMaxDynamicSharedMemorySize,
                         SMEM_TOTAL);

    init_kernel<<<1024, 256>>>(bias, dst, x, W);
    mega_kernel<<<HB + SB + GB, 256, SMEM_TOTAL>>>(al, ar, src, dst);
    agg_kernel<<<(NN * 32 + 255) / 256, 256>>>(out);
}

// round 11
// speedup vs baseline: 2.1497x; 1.0489x over previous
#include <cuda_runtime.h>
#include <cuda_fp16.h>
#include <cstdint>

#define NN   50000
#define EE   1600000
#define HH   8
#define FF   16
#define INF  256
#define HF   128
#define SLOPE 0.2f

#define SB   256            // csr scan+scatter blocks (first in mega)
#define NPB  196            // nodes per csr block
#define MTILE 128
#define KC    64
#define LDT   72            // padded fp16 row stride (144B rows)
#define GB ((NN + MTILE - 1) / MTILE)   // 391 gemm blocks

#define HIB  384            // hist blocks inside init
#define CVB  640            // convert blocks inside init

// dynamic smem layout (bytes)
#define SM_A0 0
#define SM_B0 18432
#define SM_A1 36864
#define SM_B1 55296
#define SM_AL 73728
#define SM_AR 74240
#define SMEM_TOTAL 74752

// ---------------- scratch ----------------------------------------------------
__device__ __align__(16) __half g_xh[NN * INF];     // 25.6 MB fp16 x
__device__ __align__(16) __half g_Bh[HF * INF];     // W^T fp16 [n][k]
__device__ __align__(16) __half g_feath[NN * HF];   // 12.8 MB
__device__ __half g_elh[NN * HH];
__device__ __half g_erh[NN * HH];
__device__ float g_mbias[FF];
__device__ int   g_cnt[NN];          // zero at load; re-zeroed by agg each call
__device__ int   g_off[NN + 1];
__device__ int   g_cursor[NN];
__device__ int   g_csr_src[EE];
__device__ int   g_is64;
__device__ int   g_doneA;
__device__ int   g_doneB;
__device__ int   g_blocksum[SB];

// ---------------- ptx helpers -------------------------------------------------
__device__ __forceinline__ void mma16816(float* d, unsigned a0, unsigned a1,
                                         unsigned a2, unsigned a3,
                                         unsigned b0, unsigned b1) {
    asm volatile(
        "mma.sync.aligned.m16n8k16.row.col.f32.f16.f16.f32 "
        "{%0,%1,%2,%3}, {%4,%5,%6,%7}, {%8,%9}, {%0,%1,%2,%3};"
        : "+f"(d[0]), "+f"(d[1]), "+f"(d[2]), "+f"(d[3])
        : "r"(a0), "r"(a1), "r"(a2), "r"(a3), "r"(b0), "r"(b1));
}
__device__ __forceinline__ void cpa16(uint32_t s, const void* g) {
    asm volatile("cp.async.cg.shared.global [%0], [%1], 16;" :: "r"(s), "l"(g));
}
#define CP_COMMIT() asm volatile("cp.async.commit_group;" ::: "memory")
#define CP_WAIT1()  asm volatile("cp.async.wait_group 1;" ::: "memory")
#define CP_WAIT0()  asm volatile("cp.async.wait_group 0;" ::: "memory")

// ---------------- block-local dtype detect ------------------------------------
__device__ __forceinline__ int detect_is64(const void* dstp, int tid) {
    __shared__ unsigned sany[8];
    unsigned v = ((const uint2*)dstp)[tid].y;
#pragma unroll
    for (int s = 16; s > 0; s >>= 1) v |= __shfl_xor_sync(0xffffffffu, v, s);
    if ((tid & 31) == 0) sany[tid >> 5] = v;
    __syncthreads();
    unsigned t = sany[0] | sany[1] | sany[2] | sany[3]
               | sany[4] | sany[5] | sany[6] | sany[7];
    return (t == 0u) ? 1 : 0;
}

// ---------------- init: hist (g_cnt pre-zeroed) | convert x | prep ------------
__global__ __launch_bounds__(256) void init_kernel(const float* __restrict__ bias,
                                                   const void* __restrict__ dstp,
                                                   const float* __restrict__ x,
                                                   const float* __restrict__ W) {
    int b   = blockIdx.x;
    int tid = threadIdx.x;

    if (b < HIB) {
        // ---- histogram role (cnt zeroed by previous agg / module load) ----
        int is64 = detect_is64(dstp, tid);
        if (b == 0 && tid == 0) {
            g_is64 = is64;
            g_doneA = 0;
            g_doneB = 0;
            g_off[NN] = EE;
        }
        if (b == 0 && tid < FF) {
            float s = 0.f;
#pragma unroll
            for (int h = 0; h < HH; h++) s += bias[h * FF + tid];
            g_mbias[tid] = 0.125f * s;
        }
        int stride = HIB * 256;
        for (int i = b * 256 + tid; i < EE / 2; i += stride) {
            int d0, d1;
            if (is64) {
                longlong2 v = ((const longlong2*)dstp)[i];
                d0 = (int)v.x; d1 = (int)v.y;
            } else {
                int2 v = ((const int2*)dstp)[i];
                d0 = v.x; d1 = v.y;
            }
            d0 = min(max(d0, 0), NN - 1);
            d1 = min(max(d1, 0), NN - 1);
            atomicAdd(&g_cnt[d0], 1);
            atomicAdd(&g_cnt[d1], 1);
        }
        return;
    }

    // ---- convert role ----
    int gid = (b - HIB) * 256 + tid;
    int gs  = CVB * 256;
    for (int i = gid; i < NN * INF / 4; i += gs) {
        float4 v = ((const float4*)x)[i];
        __half2 h0 = __floats2half2_rn(v.x, v.y);
        __half2 h1 = __floats2half2_rn(v.z, v.w);
        *(uint2*)&g_xh[(size_t)i * 4] =
            make_uint2(*(unsigned*)&h0, *(unsigned*)&h1);
    }
    for (int i = gid; i < HF * INF; i += gs) {
        int n = i >> 8, k = i & 255;
        g_Bh[i] = __float2half_rn(W[(size_t)k * HF + n]);
    }
}

// ---------------- mega kernel: scan+scatter | fp16-mma gemm -------------------
__global__ __launch_bounds__(256, 2)
void mega_kernel(const float* __restrict__ al,
                 const float* __restrict__ ar,
                 const void* __restrict__ srcp,
                 const void* __restrict__ dstp) {
    extern __shared__ char smem[];
    __shared__ int s_ws[8];
    __shared__ int s_red[256];

    int b   = blockIdx.x;
    int tid = threadIdx.x;

    // ======================= role 1: scan + scatter ===========================
    if (b < SB) {
        int sb = b;
        int i = sb * NPB + tid;
        int v = (tid < NPB && i < NN) ? __ldcg(&g_cnt[i]) : 0;
        int lane = tid & 31, w = tid >> 5;
        int incl = v;
#pragma unroll
        for (int s = 1; s < 32; s <<= 1) {
            int t = __shfl_up_sync(0xffffffffu, incl, s);
            if (lane >= s) incl += t;
        }
        if (lane == 31) s_ws[w] = incl;
        __syncthreads();
        if (tid == 0) {
            int run = 0;
#pragma unroll
            for (int j = 0; j < 8; j++) { int t = s_ws[j]; s_ws[j] = run; run += t; }
        }
        __syncthreads();
        incl += s_ws[w];
        int lp = incl - v;

        if (tid == 255) g_blocksum[sb] = incl;
        __threadfence();
        __syncthreads();
        if (tid == 0) {
            atomicAdd(&g_doneA, 1);
            while (atomicAdd(&g_doneA, 0) < SB) __nanosleep(128);
        }
        __syncthreads();

        s_red[tid] = (tid < sb) ? __ldcg(&g_blocksum[tid]) : 0;
        __syncthreads();
        for (int s = 128; s > 0; s >>= 1) {
            if (tid < s) s_red[tid] += s_red[tid + s];
            __syncthreads();
        }
        int base = s_red[0];

        if (tid < NPB && i < NN) {
            g_off[i]    = base + lp;
            g_cursor[i] = base + lp;
        }
        __threadfence();
        __syncthreads();
        if (tid == 0) {
            atomicAdd(&g_doneB, 1);
            while (atomicAdd(&g_doneB, 0) < SB) __nanosleep(128);
        }
        __syncthreads();

        int is64 = g_is64;
        int stride = SB * 256;
        for (int e = sb * 256 + tid; e < EE / 2; e += stride) {
            int s0, s1, d0, d1;
            if (is64) {
                longlong2 sv = ((const longlong2*)srcp)[e];
                longlong2 dv = ((const longlong2*)dstp)[e];
                s0 = (int)sv.x; s1 = (int)sv.y;
                d0 = (int)dv.x; d1 = (int)dv.y;
            } else {
                int2 sv = ((const int2*)srcp)[e];
                int2 dv = ((const int2*)dstp)[e];
                s0 = sv.x; s1 = sv.y;
                d0 = dv.x; d1 = dv.y;
            }
            s0 = min(max(s0, 0), NN - 1);
            s1 = min(max(s1, 0), NN - 1);
            d0 = min(max(d0, 0), NN - 1);
            d1 = min(max(d1, 0), NN - 1);
            int p0 = atomicAdd(&g_cursor[d0], 1);
            g_csr_src[p0] = s0;
            int p1 = atomicAdd(&g_cursor[d1], 1);
            g_csr_src[p1] = s1;
        }
        return;
    }

    // ======================= role 2: fp16 mma GEMM ============================
    int gb   = b - SB;
    int row0 = gb * MTILE;
    int wid  = tid >> 5;
    int lane = tid & 31;
    int wm   = wid >> 2;
    int wn   = wid & 3;
    uint32_t sbase = (uint32_t)__cvta_generic_to_shared(smem);
    float* salf = (float*)(smem + SM_AL);
    float* sarf = (float*)(smem + SM_AR);

    if (tid < HF) { salf[tid] = al[tid]; sarf[tid] = ar[tid]; }

    float acc[4][4][4];
#pragma unroll
    for (int mt = 0; mt < 4; mt++)
#pragma unroll
        for (int nt = 0; nt < 4; nt++)
#pragma unroll
            for (int q = 0; q < 4; q++) acc[mt][nt][q] = 0.f;

    auto load_chunk = [&](int buf, int c) {
        uint32_t abase = sbase + (buf ? SM_A1 : SM_A0);
        uint32_t bbase = sbase + (buf ? SM_B1 : SM_B0);
        for (int t = tid; t < 2048; t += 256) {
            int seg = t & 7;
            if (t < 1024) {
                int r  = t >> 3;
                int gr = row0 + r;
                if (gr < NN)
                    cpa16(abase + r * 144 + seg * 16,
                          g_xh + (size_t)gr * INF + c * KC + seg * 8);
            } else {
                int n = (t - 1024) >> 3;
                cpa16(bbase + n * 144 + seg * 16,
                      g_Bh + (size_t)n * INF + c * KC + seg * 8);
            }
        }
    };

    load_chunk(0, 0);
    CP_COMMIT();
    for (int c = 0; c < 4; c++) {
        if (c < 3) {
            load_chunk((c + 1) & 1, c + 1);
            CP_COMMIT();
            CP_WAIT1();
        } else {
            CP_WAIT0();
        }
        __syncthreads();
        __half* sA = (__half*)(smem + ((c & 1) ? SM_A1 : SM_A0));
        __half* sB = (__half*)(smem + ((c & 1) ? SM_B1 : SM_B0));
#pragma unroll
        for (int ks = 0; ks < 4; ks++) {
            int koff = ks * 16 + (lane & 3) * 2;
            unsigned bf[4][2];
#pragma unroll
            for (int nt = 0; nt < 4; nt++) {
                int n = (wn * 32 + nt * 8 + (lane >> 2)) * LDT + koff;
                bf[nt][0] = *(const unsigned*)&sB[n];
                bf[nt][1] = *(const unsigned*)&sB[n + 8];
            }
#pragma unroll
            for (int mt = 0; mt < 4; mt++) {
                int r = (wm * 64 + mt * 16 + (lane >> 2)) * LDT + koff;
                unsigned a0 = *(const unsigned*)&sA[r];
                unsigned a1 = *(const unsigned*)&sA[r + 8 * LDT];
                unsigned a2 = *(const unsigned*)&sA[r + 8];
                unsigned a3 = *(const unsigned*)&sA[r + 8 * LDT + 8];
#pragma unroll
                for (int nt = 0; nt < 4; nt++)
                    mma16816(acc[mt][nt], a0, a1, a2, a3, bf[nt][0], bf[nt][1]);
            }
        }
        __syncthreads();
    }

    // epilogue: fp16 feat store + el/er from registers
#pragma unroll
    for (int mt = 0; mt < 4; mt++) {
        int rr0 = row0 + wm * 64 + mt * 16 + (lane >> 2);
        int rr1 = rr0 + 8;
        float el0[2] = {0.f, 0.f}, er0[2] = {0.f, 0.f};
        float el1[2] = {0.f, 0.f}, er1[2] = {0.f, 0.f};
#pragma unroll
        for (int nt = 0; nt < 4; nt++) {
            int col  = wn * 32 + nt * 8 + (lane & 3) * 2;
            int hsel = nt >> 1;
            float d0 = acc[mt][nt][0], d1 = acc[mt][nt][1];
            float d2 = acc[mt][nt][2], d3 = acc[mt][nt][3];
            el0[hsel] += d0 * salf[col] + d1 * salf[col + 1];
            er0[hsel] += d0 * sarf[col] + d1 * sarf[col + 1];
            el1[hsel] += d2 * salf[col] + d3 * salf[col + 1];
            er1[hsel] += d2 * sarf[col] + d3 * sarf[col + 1];
            if (rr0 < NN) {
                __half2 p = __floats2half2_rn(d0, d1);
                *(unsigned*)&g_feath[(size_t)rr0 * HF + col] = *(unsigned*)&p;
            }
            if (rr1 < NN) {
                __half2 p = __floats2half2_rn(d2, d3);
                *(unsigned*)&g_feath[(size_t)rr1 * HF + col] = *(unsigned*)&p;
            }
        }
#pragma unroll
        for (int s = 1; s <= 2; s <<= 1) {
            el0[0] += __shfl_xor_sync(0xffffffffu, el0[0], s);
            el0[1] += __shfl_xor_sync(0xffffffffu, el0[1], s);
            er0[0] += __shfl_xor_sync(0xffffffffu, er0[0], s);
            er0[1] += __shfl_xor_sync(0xffffffffu, er0[1], s);
            el1[0] += __shfl_xor_sync(0xffffffffu, el1[0], s);
            el1[1] += __shfl_xor_sync(0xffffffffu, el1[1], s);
            er1[0] += __shfl_xor_sync(0xffffffffu, er1[0], s);
            er1[1] += __shfl_xor_sync(0xffffffffu, er1[1], s);
        }
        if ((lane & 3) == 0) {
            if (rr0 < NN) {
                g_elh[rr0 * HH + 2 * wn]     = __float2half_rn(el0[0]);
                g_elh[rr0 * HH + 2 * wn + 1] = __float2half_rn(el0[1]);
                g_erh[rr0 * HH + 2 * wn]     = __float2half_rn(er0[0]);
                g_erh[rr0 * HH + 2 * wn + 1] = __float2half_rn(er0[1]);
            }
            if (rr1 < NN) {
                g_elh[rr1 * HH + 2 * wn]     = __float2half_rn(el1[0]);
                g_elh[rr1 * HH + 2 * wn + 1] = __float2half_rn(el1[1]);
                g_erh[rr1 * HH + 2 * wn]     = __float2half_rn(er1[0]);
                g_erh[rr1 * HH + 2 * wn + 1] = __float2half_rn(er1[1]);
            }
        }
    }
}

// ---------------- fused softmax-aggregate + classifier + cnt reset ------------
__global__ __launch_bounds__(256) void agg_kernel(float* __restrict__ out) {
    int gtid = blockIdx.x * blockDim.x + threadIdx.x;
    // re-zero g_cnt for the next kernel_launch invocation (graph replay)
    if (gtid < NN) g_cnt[gtid] = 0;

    int n    = gtid >> 5;
    int lane = gtid & 31;
    if (n >= NN) return;
    int g   = lane >> 3;
    int sub = lane & 7;
    unsigned gm = 0xFFu << (g * 8);

    float ern = __half2float(g_erh[n * HH + sub]);
    int beg = g_off[n], end = g_off[n + 1];

    float accL[8], accH[8];
#pragma unroll
    for (int k = 0; k < 8; k++) { accL[k] = 0.f; accH[k] = 0.f; }
    float ssum = 0.f;

    int i  = beg + g;
    int sv = (i < end) ? g_csr_src[i] : -1;
    while (sv >= 0) {
        int ni  = i + 4;
        int nsv = (ni < end) ? g_csr_src[ni] : -1;
        const uint4* fp = (const uint4*)(g_feath + (size_t)sv * HF);
        uint4 f0 = fp[sub];
        uint4 f1 = fp[8 + sub];
        float e = __half2float(g_elh[sv * HH + sub]) + ern;
        e = fmaxf(e, 0.f) + SLOPE * fminf(e, 0.f);
        float exv = __expf(e);
        ssum += exv;
        float exL = __shfl_sync(gm, exv, (g << 3) + (sub >> 1));
        float exH = __shfl_sync(gm, exv, (g << 3) + 4 + (sub >> 1));
        float2 a0 = __half22float2(*reinterpret_cast<__half2*>(&f0.x));
        float2 a1 = __half22float2(*reinterpret_cast<__half2*>(&f0.y));
        float2 a2 = __half22float2(*reinterpret_cast<__half2*>(&f0.z));
        float2 a3 = __half22float2(*reinterpret_cast<__half2*>(&f0.w));
        float2 b0 = __half22float2(*reinterpret_cast<__half2*>(&f1.x));
        float2 b1 = __half22float2(*reinterpret_cast<__half2*>(&f1.y));
        float2 b2 = __half22float2(*reinterpret_cast<__half2*>(&f1.z));
        float2 b3 = __half22float2(*reinterpret_cast<__half2*>(&f1.w));
        accL[0] += exL * a0.x; accL[1] += exL * a0.y;
        accL[2] += exL * a1.x; accL[3] += exL * a1.y;
        accL[4] += exL * a2.x; accL[5] += exL * a2.y;
        accL[6] += exL * a3.x; accL[7] += exL * a3.y;
        accH[0] += exH * b0.x; accH[1] += exH * b0.y;
        accH[2] += exH * b1.x; accH[3] += exH * b1.y;
        accH[4] += exH * b2.x; accH[5] += exH * b2.y;
        accH[6] += exH * b3.x; accH[7] += exH * b3.y;
        i = ni; sv = nsv;
    }
    __syncwarp(0xffffffffu);

#pragma unroll
    for (int k = 0; k < 8; k++) {
        accL[k] += __shfl_xor_sync(0xffffffffu, accL[k], 8);
        accL[k] += __shfl_xor_sync(0xffffffffu, accL[k], 16);
        accH[k] += __shfl_xor_sync(0xffffffffu, accH[k], 8);
        accH[k] += __shfl_xor_sync(0xffffffffu, accH[k], 16);
    }
    ssum += __shfl_xor_sync(0xffffffffu, ssum, 8);
    ssum += __shfl_xor_sync(0xffffffffu, ssum, 16);

    float inv  = 1.f / fmaxf(ssum, 1e-9f);
    float invL = __shfl_sync(0xffffffffu, inv, (lane & 24) + (sub >> 1));
    float invH = __shfl_sync(0xffffffffu, inv, (lane & 24) + 4 + (sub >> 1));

    float v[8];
#pragma unroll
    for (int k = 0; k < 8; k++) v[k] = accL[k] * invL + accH[k] * invH;

#pragma unroll
    for (int k = 0; k < 8; k++) {
        v[k] += __shfl_xor_sync(0xffffffffu, v[k], 2);
        v[k] += __shfl_xor_sync(0xffffffffu, v[k], 4);
    }

    if (lane < 2) {
        float4 o0, o1;
        o0.x = v[0] * 0.125f + g_mbias[lane * 8 + 0];
        o0.y = v[1] * 0.125f + g_mbias[lane * 8 + 1];
        o0.z = v[2] * 0.125f + g_mbias[lane * 8 + 2];
        o0.w = v[3] * 0.125f + g_mbias[lane * 8 + 3];
        o1.x = v[4] * 0.125f + g_mbias[lane * 8 + 4];
        o1.y = v[5] * 0.125f + g_mbias[lane * 8 + 5];
        o1.z = v[6] * 0.125f + g_mbias[lane * 8 + 6];
        o1.w = v[7] * 0.125f + g_mbias[lane * 8 + 7];
        ((float4*)out)[n * 4 + lane * 2 + 0] = o0;
        ((float4*)out)[n * 4 + lane * 2 + 1] = o1;
    }
}

// ---------------- launch ------------------------------------------------------
extern "C" void kernel_launch(void* const* d_in, const int* in_sizes, int n_in,
                              void* d_out, int out_size) {
    const float* x    = (const float*)d_in[0];
    const float* W    = (const float*)d_in[1];
    const float* al   = (const float*)d_in[2];
    const float* ar   = (const float*)d_in[3];
    const float* bias = (const float*)d_in[4];
    const void*  src  = d_in[5];
    const void*  dst  = d_in[6];
    float* out = (float*)d_out;

    cudaFuncSetAttribute(mega_kernel, cudaFuncAttributeMaxDynamicSharedMemorySize,
                         SMEM_TOTAL);

    init_kernel<<<HIB + CVB, 256>>>(bias, dst, x, W);
    mega_kernel<<<SB + GB, 256, SMEM_TOTAL>>>(al, ar, src, dst);
    agg_kernel<<<(NN * 32 + 255) / 256, 256>>>(out);
}